// round 9
// baseline (speedup 1.0000x reference)
#include <cuda_runtime.h>
#include <stdint.h>

// PicMix: output = two index-function masks, no input read.
// Flattened: [mask_a (8,12,512,512) fp32][mask_b same]. 192 planes of 512x512.
// group g = (ch%12)/3; isB = second mask.
//   g0: a=1,b=0 | g1: a=(i%2==j%2) | g2: a=i%2 | g3: a=j%2 ; b = complement.
// Each float4 covers j..j+3 (even start) -> lanes are (even,odd,even,odd).
//
// FINAL: 12288 CTAs x 256 thr x 4 float4/thread (measured sweep optimum,
// ncu 27.71us). Thread stride = 256 f4 = exactly 2 rows, so row parity (and
// the store value) is constant per thread: decode once, 4x STG.E.128 at
// immediate offsets.
//
// Session evidence (7 mechanisms: STG.128 at 5 grid shapes, STG.CS, STG.256,
// TMA bulk-store): all plateau at 27.7-30.7us ncu / 58-64% DRAM. The limiter
// is the path-independent chip LTS store ceiling (~7.25 TB/s L2-side); the
// 201.3 MB output is irreducible, so ~27.7us is the floor and this config
// sits on it.

static constexpr int PLANE_F4         = 65536;  // 512*512/4
static constexpr int BLOCKS_PER_PLANE = 64;
static constexpr int F4_PER_BLOCK     = PLANE_F4 / BLOCKS_PER_PLANE; // 1024
static constexpr int THREADS          = 256;
static constexpr int F4_PER_THREAD    = F4_PER_BLOCK / THREADS;      // 4

__global__ void __launch_bounds__(THREADS) picmix_kernel(float4* __restrict__ out) {
    int plane = blockIdx.x >> 6;        // BLOCKS_PER_PLANE = 64
    int seg   = blockIdx.x & 63;

    int base = plane * PLANE_F4 + seg * F4_PER_BLOCK + threadIdx.x;
    int ip   = (base >> 7) & 1;         // row parity; invariant across strided stores

    int isB = plane >= 96;              // 96 planes per mask
    int pin = isB ? plane - 96 : plane;
    int ch  = pin % 12;
    int g   = ch * 0x5556 >> 16;        // ch/3 for ch in [0,12)

    float e, o;                         // even-j value, odd-j value
    if (g == 0) {
        e = o = isB ? 0.0f : 1.0f;
    } else if (g == 1) {
        float s = (ip == 0) ? 1.0f : 0.0f;   // mask_a even lane
        e = isB ? 1.0f - s : s;
        o = 1.0f - e;
    } else if (g == 2) {
        float v = (float)ip;
        e = o = isB ? 1.0f - v : v;
    } else {
        e = isB ? 1.0f : 0.0f;
        o = 1.0f - e;
    }

    float4 v4 = make_float4(e, o, e, o);
    float4* p = out + base;
    #pragma unroll
    for (int k = 0; k < F4_PER_THREAD; k++) {
        p[k * THREADS] = v4;            // stride 256 f4 = 4KB = 2 rows
    }
}

extern "C" void kernel_launch(void* const* d_in, const int* in_sizes, int n_in,
                              void* d_out, int out_size) {
    (void)d_in; (void)in_sizes; (void)n_in; (void)out_size;
    // out_size = 50,331,648 fp32 = 192 planes * 65536 f4
    int blocks = 192 * BLOCKS_PER_PLANE;  // 12288
    picmix_kernel<<<blocks, THREADS>>>((float4*)d_out);
}

// round 10
// speedup vs baseline: 1.0082x; 1.0082x over previous
#include <cuda_runtime.h>
#include <stdint.h>

// PicMix: output = two index-function masks, no input read.
// Flattened: [mask_a (8,12,512,512) fp32][mask_b same]. 192 planes of 512x512.
// group g = (ch%12)/3; isB = second mask.
//   g0: a=1,b=0 | g1: a=(i%2==j%2) | g2: a=i%2 | g3: a=j%2 ; b = complement.
// Each float4 covers j..j+3 (even start) -> lanes are (even,odd,even,odd).
//
// FINAL: 12288 CTAs x 256 thr x 4 float4/thread (measured sweep optimum;
// ncu 27.7-28.3us across repeat runs). Thread stride = 256 f4 = exactly
// 2 rows, so row parity (and the store value) is constant per thread:
// decode once, 4x STG.E.128 at immediate offsets.
//
// Session evidence (9 rounds, 7 mechanisms: STG.128 at 5 grid shapes,
// STG.CS, STG.256, TMA bulk-store): all plateau at 27.7-30.7us ncu /
// 58-65% DRAM. Limiter = path-independent chip LTS store ceiling
// (~7.2 TB/s L2-side, ~6300 B/cyc). 201.3 MB output is irreducible
// (exact fp32 0/1 planes, poisoned buffer), so ~28us is the hard floor
// and this config sits on it; residual config differences are within the
// +/-0.6us run-to-run jitter.

static constexpr int PLANE_F4         = 65536;  // 512*512/4
static constexpr int BLOCKS_PER_PLANE = 64;
static constexpr int F4_PER_BLOCK     = PLANE_F4 / BLOCKS_PER_PLANE; // 1024
static constexpr int THREADS          = 256;
static constexpr int F4_PER_THREAD    = F4_PER_BLOCK / THREADS;      // 4

__global__ void __launch_bounds__(THREADS) picmix_kernel(float4* __restrict__ out) {
    int plane = blockIdx.x >> 6;        // BLOCKS_PER_PLANE = 64
    int seg   = blockIdx.x & 63;

    int base = plane * PLANE_F4 + seg * F4_PER_BLOCK + threadIdx.x;
    int ip   = (base >> 7) & 1;         // row parity; invariant across strided stores

    int isB = plane >= 96;              // 96 planes per mask
    int pin = isB ? plane - 96 : plane;
    int ch  = pin % 12;
    int g   = ch * 0x5556 >> 16;        // ch/3 for ch in [0,12)

    float e, o;                         // even-j value, odd-j value
    if (g == 0) {
        e = o = isB ? 0.0f : 1.0f;
    } else if (g == 1) {
        float s = (ip == 0) ? 1.0f : 0.0f;   // mask_a even lane
        e = isB ? 1.0f - s : s;
        o = 1.0f - e;
    } else if (g == 2) {
        float v = (float)ip;
        e = o = isB ? 1.0f - v : v;
    } else {
        e = isB ? 1.0f : 0.0f;
        o = 1.0f - e;
    }

    float4 v4 = make_float4(e, o, e, o);
    float4* p = out + base;
    #pragma unroll
    for (int k = 0; k < F4_PER_THREAD; k++) {
        p[k * THREADS] = v4;            // stride 256 f4 = 4KB = 2 rows
    }
}

extern "C" void kernel_launch(void* const* d_in, const int* in_sizes, int n_in,
                              void* d_out, int out_size) {
    (void)d_in; (void)in_sizes; (void)n_in; (void)out_size;
    // out_size = 50,331,648 fp32 = 192 planes * 65536 f4
    int blocks = 192 * BLOCKS_PER_PLANE;  // 12288
    picmix_kernel<<<blocks, THREADS>>>((float4*)d_out);
}